// round 14
// baseline (speedup 1.0000x reference)
#include <cuda_runtime.h>
#include <cuda_bf16.h>
#include <math.h>
#include <cstdint>

#define Nn 8192
#define Dd 128
#define Cc 512
#define ALPHA 0.2f
#define ALPHA_BITS 0x3E4CCCCDu   // bit pattern of 0.2f
#define NTILE 64
#define KSRC 256             // buf row: [hi(128), lo(128)]
#define BK 64
#define KCHUNKS 4
#define NSTAGE 3
#define TILEB 16384          // 128 rows * 64 bf16 * 2B
#define DYN_SMEM (1024 + 2 * NSTAGE * TILEB)
#define SORT_SMEM (32768 + 131072 + 2048)
#define NANCH 256            // anchor blocks (64 j-tiles x 4 label-tiles)

// ---------------- device scratch ----------------
__device__ float  g_sq [Nn];
__device__ float  g_ap [Nn];
__device__ int    g_lab[Nn];
__device__ int    g_perm[Nn];
__device__ int    g_pos [Nn];
__device__ int    g_offset[Cc + 1];
__device__ __nv_bfloat16 g_Abuf[(size_t)Nn * KSRC];
__device__ __nv_bfloat16 g_Anc [(size_t)Cc * KSRC];
__device__ float  g_sqA[Cc];
__device__ double g_acc;
__device__ int    g_done;

// ---------------- PTX helpers ----------------
__device__ __forceinline__ uint32_t smem_u32(const void* p) {
    uint32_t a;
    asm("{ .reg .u64 t; cvta.to.shared.u64 t, %1; cvt.u32.u64 %0, t; }" : "=r"(a) : "l"(p));
    return a;
}
__device__ __forceinline__ void cpasync16(uint32_t s, const void* g) {
    asm volatile("cp.async.cg.shared.global [%0], [%1], 16;" :: "r"(s), "l"(g));
}
__device__ __forceinline__ void cp_commit() {
    asm volatile("cp.async.commit_group;" ::: "memory");
}
template <int N>
__device__ __forceinline__ void cp_wait() {
    asm volatile("cp.async.wait_group %0;" :: "n"(N) : "memory");
}
__device__ __forceinline__ void ldm_x4(uint32_t& r0, uint32_t& r1, uint32_t& r2,
                                       uint32_t& r3, uint32_t addr) {
    asm volatile("ldmatrix.sync.aligned.m8n8.x4.shared.b16 {%0,%1,%2,%3}, [%4];"
                 : "=r"(r0), "=r"(r1), "=r"(r2), "=r"(r3) : "r"(addr));
}
__device__ __forceinline__ void mma16816(float* c, uint32_t a0, uint32_t a1,
                                         uint32_t a2, uint32_t a3,
                                         uint32_t b0, uint32_t b1) {
    asm volatile(
        "mma.sync.aligned.m16n8k16.row.col.f32.bf16.bf16.f32 "
        "{%0,%1,%2,%3}, {%4,%5,%6,%7}, {%8,%9}, {%0,%1,%2,%3};"
        : "+f"(c[0]), "+f"(c[1]), "+f"(c[2]), "+f"(c[3])
        : "r"(a0), "r"(a1), "r"(a2), "r"(a3), "r"(b0), "r"(b1));
}
// single-ISETP hinge: contribute t iff 0 < t < ALPHA (t==0 adds 0.0, harmless)
__device__ __forceinline__ void hinge(float t, float& s) {
    if (__float_as_uint(t) < ALPHA_BITS) s += t;
}

// ---------------- stable counting sort, all-smem (one block) ----------------
__global__ void __launch_bounds__(512, 1) k_sort(const int* __restrict__ labels) {
    extern __shared__ char sm[];
    int*      slab  = (int*)sm;
    uint8_t*  hh    = (uint8_t*)(sm + 32768);
    int*      sscan = (int*)(sm + 32768 + 131072);
    __shared__ int wtot[16];
    int tid = threadIdx.x;
    int lane = tid & 31, wrp = tid >> 5;

    if (tid == 0) { g_acc = 0.0; g_done = 0; }

    for (int q = tid; q < Nn; q += 512) slab[q] = labels[q];
    {
        uint32_t* h4 = (uint32_t*)hh;
        for (int q = tid; q < 32768; q += 512) h4[q] = 0;
    }
    __syncthreads();

    if (tid < 256) {
        int base = tid * 32;
#pragma unroll
        for (int q = 0; q < 32; q++) {
            int l = slab[base + q];
            hh[l * 256 + tid] += 1;
        }
    }
    __syncthreads();

    // per-label exclusive prefix over chunks (SWAR) -> per-label total in v
    int v;
    {
        uint32_t run = 0;
        uint32_t* row = (uint32_t*)&hh[tid * 256];
#pragma unroll 8
        for (int w = 0; w < 64; w++) {
            uint32_t x = row[w];
            uint32_t p = x + (x << 8);
            p = p + (p << 16);
            row[w] = (p << 8) + run * 0x01010101u;
            run += (p >> 24);
        }
        v = (int)run;
    }

    // inclusive scan over 512 labels: warp shuffle scan + warp-total scan
#pragma unroll
    for (int o = 1; o < 32; o <<= 1) {
        int n = __shfl_up_sync(0xffffffffu, v, o);
        if (lane >= o) v += n;
    }
    if (lane == 31) wtot[wrp] = v;
    __syncthreads();
    if (wrp == 0) {
        int w = (lane < 16) ? wtot[lane] : 0;
#pragma unroll
        for (int o = 1; o < 16; o <<= 1) {
            int n = __shfl_up_sync(0xffffffffu, w, o);
            if (lane >= o) w += n;
        }
        if (lane < 16) wtot[lane] = w;
    }
    __syncthreads();
    int incl = v + (wrp ? wtot[wrp - 1] : 0);
    sscan[tid] = incl;
    g_offset[tid + 1] = incl;
    if (tid == 0) g_offset[0] = 0;
    __syncthreads();

    if (tid < 256) {
        int base = tid * 32;
        int labs[32];
#pragma unroll
        for (int q = 0; q < 32; q++) labs[q] = slab[base + q];
#pragma unroll
        for (int q = 0; q < 32; q++) {
            int l = labs[q];
            int r = 0;
#pragma unroll
            for (int p = 0; p < 32; p++)
                if (p < q && labs[p] == l) r++;
            int off = (l == 0) ? 0 : sscan[l - 1];
            int pos = off + (int)hh[l * 256 + tid] + r;
            g_perm[pos] = base + q;
            g_lab[pos]  = l;
        }
    }
}

// ---------------- prep: warp-per-row gather/split/norms/ap ------------------
__global__ void __launch_bounds__(256, 8) k_prep(const float* __restrict__ X) {
    int wid = threadIdx.x >> 5, lane = threadIdx.x & 31;
    int row = blockIdx.x * 8 + wid;
    int l = g_lab[row];
    int a = g_offset[l];
    int orig  = g_perm[row];
    int origA = g_perm[a];

    float4 v  = ((const float4*)(X + (size_t)orig  * Dd))[lane];
    float4 va = ((const float4*)(X + (size_t)origA * Dd))[lane];

    __nv_bfloat162 h01, h23, l01, l23;
    h01.x = __float2bfloat16(v.x); h01.y = __float2bfloat16(v.y);
    h23.x = __float2bfloat16(v.z); h23.y = __float2bfloat16(v.w);
    l01.x = __float2bfloat16(v.x - __bfloat162float(h01.x));
    l01.y = __float2bfloat16(v.y - __bfloat162float(h01.y));
    l23.x = __float2bfloat16(v.z - __bfloat162float(h23.x));
    l23.y = __float2bfloat16(v.w - __bfloat162float(h23.y));
    uint2 hi2 = make_uint2(*(uint32_t*)&h01, *(uint32_t*)&h23);
    uint2 lo2 = make_uint2(*(uint32_t*)&l01, *(uint32_t*)&l23);
    size_t b = (size_t)row * KSRC;
    *(uint2*)(g_Abuf + b + lane * 4)       = hi2;
    *(uint2*)(g_Abuf + b + 128 + lane * 4) = lo2;
    if (row == a) {
        size_t ba = (size_t)l * KSRC;
        *(uint2*)(g_Anc + ba + lane * 4)       = hi2;
        *(uint2*)(g_Anc + ba + 128 + lane * 4) = lo2;
    }

    float s1 = v.x * v.x + v.y * v.y + v.z * v.z + v.w * v.w;
    float s2 = va.x * va.x + va.y * va.y + va.z * va.z + va.w * va.w;
    float s3 = v.x * va.x + v.y * va.y + v.z * va.z + v.w * va.w;
#pragma unroll
    for (int o = 16; o > 0; o >>= 1) {
        s1 += __shfl_down_sync(0xffffffffu, s1, o);
        s2 += __shfl_down_sync(0xffffffffu, s2, o);
        s3 += __shfl_down_sync(0xffffffffu, s3, o);
    }
    if (lane == 0) {
        g_sq[row]  = s1;
        g_ap[row]  = s2 + s1 - 2.0f * s3;
        g_pos[row] = (row != a) ? 1 : 0;
        if (row == a) g_sqA[l] = s1;
    }
}

// ---------------- fused: anchor blocks (0..255) + main tiles (256..2335) ----
// also writes the final scalar output from the last-finishing block
__global__ void __launch_bounds__(256, 2) k_fused(float* __restrict__ out) {
    extern __shared__ char dynsm[];
    __shared__ float sSqI[128], sSqJ[128], sApIA[128], sApJA[128];
    __shared__ int   sLabI[128], sLabJ[128];
    __shared__ int   sOff[129];
    __shared__ float sSqA[128];
    __shared__ float warpsum[8];

    int tid = threadIdx.x;
    int wid = tid >> 5, lane = tid & 31;
    int wm = wid & 3, wn = wid >> 2;
    int lrow = lane & 15, lkh = lane >> 4;
    int tg = lane & 3, gID = lane >> 2;

    int bid = blockIdx.x;
    int is_anch = (bid < NANCH);
    int i0 = 0, j0, l0 = 0, by = 0, bx = 0, offdiag = 0;
    const __nv_bfloat16 *aSrc, *bSrc;

    if (is_anch) {
        j0 = (bid & 63) * 128;
        l0 = (bid >> 6) * 128;
        aSrc = g_Anc  + (size_t)l0 * KSRC;
        bSrc = g_Abuf + (size_t)j0 * KSRC;
    } else {
        int t = bid - NANCH;
        by = (int)(0.5f * (129.0f - sqrtf(16641.0f - 8.0f * (float)t)));
        while ((by + 1) * NTILE - (((by + 1) * by) >> 1) <= t) by++;
        while (by * NTILE - ((by * (by - 1)) >> 1) > t) by--;
        bx = by + t - (by * NTILE - ((by * (by - 1)) >> 1));
        i0 = by * 128; j0 = bx * 128;
        offdiag = (bx != by);
        aSrc = g_Abuf + (size_t)i0 * KSRC;
        bSrc = g_Abuf + (size_t)j0 * KSRC;
    }

    uint32_t dbase = smem_u32(dynsm);
    uint32_t smBase = (dbase + 1023u) & ~1023u;

    if (is_anch) {
        if (tid < 129) sOff[tid] = g_offset[l0 + tid];
        if (tid < 128) sSqJ[tid] = g_sq[j0 + tid];
        else if (tid >= 128) sSqA[tid - 128] = g_sqA[l0 + tid - 128];
    } else {
        if (tid < 128) {
            int i = i0 + tid;
            sSqI[tid]  = g_sq[i];
            sLabI[tid] = g_lab[i];
            sApIA[tid] = g_pos[i] ? (g_ap[i] + ALPHA) : -1e30f;
        } else {
            int tt2 = tid - 128;
            int j = j0 + tt2;
            sSqJ[tt2]  = g_sq[j];
            sLabJ[tt2] = g_lab[j];
            sApJA[tt2] = (offdiag && g_pos[j]) ? (g_ap[j] + ALPHA) : -1e30f;
        }
    }

    float acc[2][8][4];
#pragma unroll
    for (int a = 0; a < 2; a++)
#pragma unroll
        for (int b = 0; b < 8; b++)
#pragma unroll
            for (int e = 0; e < 4; e++) acc[a][b][e] = 0.0f;

    int lr[4], ls[4];
    uint32_t loff[4];
#pragma unroll
    for (int p = 0; p < 4; p++) {
        int q = tid + p * 256;
        lr[p] = q >> 3;
        ls[p] = q & 7;
        loff[p] = (uint32_t)lr[p] * 128u + (((uint32_t)ls[p] * 16u) ^ (((uint32_t)lr[p] & 7u) << 4));
    }

    // prefetch chunks 0,1
#pragma unroll
    for (int c0 = 0; c0 < NSTAGE - 1; c0++) {
        uint32_t sA = smBase + (uint32_t)c0 * 2u * TILEB;
        uint32_t sB = sA + TILEB;
        int kk = c0 * BK;
#pragma unroll
        for (int p = 0; p < 4; p++) {
            cpasync16(sA + loff[p], aSrc + (size_t)lr[p] * KSRC + kk + ls[p] * 8);
            cpasync16(sB + loff[p], bSrc + (size_t)lr[p] * KSRC + kk + ls[p] * 8);
        }
        cp_commit();
    }

    int arow = wm * 32 + lrow;
    uint32_t aOff = (uint32_t)arow * 128u;
    uint32_t aXor = ((uint32_t)arow & 7u) << 4;

    // single-sync pipeline: [cp_wait][sync][issue c+2][consume c]
    for (int c = 0; c < KCHUNKS; c++) {
        if (c < KCHUNKS - 1) cp_wait<NSTAGE - 2>();
        else                 cp_wait<0>();
        __syncthreads();
        if (c + NSTAGE - 1 < KCHUNKS) {
            int cn = c + NSTAGE - 1;
            int kk = cn * BK;
            uint32_t sA = smBase + (uint32_t)(cn % NSTAGE) * 2u * TILEB;
            uint32_t sB = sA + TILEB;
#pragma unroll
            for (int p = 0; p < 4; p++) {
                cpasync16(sA + loff[p], aSrc + (size_t)lr[p] * KSRC + kk + ls[p] * 8);
                cpasync16(sB + loff[p], bSrc + (size_t)lr[p] * KSRC + kk + ls[p] * 8);
            }
            cp_commit();
        }

        uint32_t aB = smBase + (uint32_t)(c % NSTAGE) * 2u * TILEB;
        uint32_t bB = aB + TILEB;
#pragma unroll
        for (int ks = 0; ks < 4; ks++) {
            uint32_t koff = (uint32_t)(ks * 32 + lkh * 16);
            uint32_t a0[2], a1[2], a2[2], a3[2];
#pragma unroll
            for (int mi = 0; mi < 2; mi++)
                ldm_x4(a0[mi], a1[mi], a2[mi], a3[mi],
                       aB + aOff + (uint32_t)mi * 2048u + (koff ^ aXor));
#pragma unroll
            for (int g2 = 0; g2 < 4; g2++) {
                int brow = wn * 64 + g2 * 16 + lrow;
                uint32_t r0, r1, r2, r3;
                ldm_x4(r0, r1, r2, r3,
                       bB + (uint32_t)brow * 128u + (koff ^ (((uint32_t)brow & 7u) << 4)));
#pragma unroll
                for (int mi = 0; mi < 2; mi++) {
                    mma16816(acc[mi][2 * g2],     a0[mi], a1[mi], a2[mi], a3[mi], r0, r2);
                    mma16816(acc[mi][2 * g2 + 1], a0[mi], a1[mi], a2[mi], a3[mi], r1, r3);
                }
            }
        }
    }

    float csum0 = 0.0f, csum1 = 0.0f;

    if (is_anch) {
        // all warps must finish reading tile smem before reuse for sap
        __syncthreads();
        float* sap = (float*)dynsm;
        int apbase = sOff[0];
        int apcnt  = sOff[128] - apbase;
        for (int q = tid; q < apcnt; q += 256) sap[q] = g_ap[apbase + q];
        __syncthreads();

#pragma unroll
        for (int ridx = 0; ridx < 4; ridx++) {
            int mi = ridx >> 1, e2 = ridx & 1;
            int row = wm * 32 + mi * 16 + gID + e2 * 8;
            int s0 = sOff[row], s1 = sOff[row + 1];
            int m = s1 - s0 - 1;
            if (m > 0) {
                float nsqaA = ALPHA - sSqA[row];
                float negD[16];
#pragma unroll
                for (int ni = 0; ni < 8; ni++)
#pragma unroll
                    for (int e1 = 0; e1 < 2; e1++) {
                        int col = wn * 64 + ni * 8 + 2 * tg + e1;
                        int j = j0 + col;
                        float nd = fmaf(2.0f, acc[mi][ni][e2 * 2 + e1], nsqaA - sSqJ[col]);
                        negD[ni * 2 + e1] = (j >= s0 && j < s1) ? -1e30f : nd;
                    }
                int qb = s0 - apbase + 1;
                for (int q = 0; q < m; q++) {
                    float apq = sap[qb + q];
#pragma unroll
                    for (int c16 = 0; c16 < 16; c16 += 2) {
                        hinge(apq + negD[c16],     csum0);
                        hinge(apq + negD[c16 + 1], csum1);
                    }
                }
            }
        }
    } else {
        float rSq[4], rC[4];
        int   rLab[4];
#pragma unroll
        for (int mi = 0; mi < 2; mi++)
#pragma unroll
            for (int e2 = 0; e2 < 2; e2++) {
                int ridx = mi * 2 + e2;
                int row = wm * 32 + mi * 16 + gID + e2 * 8;
                rSq[ridx]  = sSqI[row];
                rLab[ridx] = sLabI[row];
                rC[ridx]   = sApIA[row] - rSq[ridx];
            }

        int collide = (by == bx) || (sLabI[127] == sLabJ[0]);

        if (!collide) {
#pragma unroll
            for (int ni = 0; ni < 8; ni++)
#pragma unroll
                for (int e1 = 0; e1 < 2; e1++) {
                    int col = wn * 64 + ni * 8 + 2 * tg + e1;
                    float cSq = sSqJ[col];
                    float cC  = sApJA[col] - cSq;
#pragma unroll
                    for (int mi = 0; mi < 2; mi++)
#pragma unroll
                        for (int e2 = 0; e2 < 2; e2++) {
                            int ridx = mi * 2 + e2;
                            float av = acc[mi][ni][e2 * 2 + e1];
                            hinge(fmaf(2.0f, av, rC[ridx] - cSq), csum0);
                            hinge(fmaf(2.0f, av, cC - rSq[ridx]), csum1);
                        }
                }
        } else {
#pragma unroll
            for (int ni = 0; ni < 8; ni++)
#pragma unroll
                for (int e1 = 0; e1 < 2; e1++) {
                    int col = wn * 64 + ni * 8 + 2 * tg + e1;
                    float cSq = sSqJ[col];
                    float cC  = sApJA[col] - cSq;
                    int   cLab = sLabJ[col];
#pragma unroll
                    for (int mi = 0; mi < 2; mi++)
#pragma unroll
                        for (int e2 = 0; e2 < 2; e2++) {
                            int ridx = mi * 2 + e2;
                            if (rLab[ridx] == cLab) continue;
                            float av = acc[mi][ni][e2 * 2 + e1];
                            hinge(fmaf(2.0f, av, rC[ridx] - cSq), csum0);
                            hinge(fmaf(2.0f, av, cC - rSq[ridx]), csum1);
                        }
                }
        }
    }

    float csum = csum0 + csum1;
#pragma unroll
    for (int o = 16; o > 0; o >>= 1) csum += __shfl_down_sync(0xffffffffu, csum, o);
    if (lane == 0) warpsum[wid] = csum;
    __syncthreads();
    if (wid == 0) {
        float tt2 = (lane < 8) ? warpsum[lane] : 0.0f;
#pragma unroll
        for (int o = 4; o > 0; o >>= 1) tt2 += __shfl_down_sync(0xffffffffu, tt2, o);
        if (lane == 0) atomicAdd(&g_acc, (double)tt2);
    }

    // completion-counter tail: last block writes the scalar output
    __syncthreads();
    if (tid == 0) {
        __threadfence();
        int old = atomicAdd(&g_done, 1);
        if (old == (int)gridDim.x - 1) {
            __threadfence();
            out[0] = (float)g_acc;
        }
    }
}

// ---------------- launch ----------------
extern "C" void kernel_launch(void* const* d_in, const int* in_sizes, int n_in,
                              void* d_out, int out_size) {
    const float* X      = (const float*)d_in[0];
    const int*   labels = (const int*)d_in[1];

    static int smem_set = 0;
    if (!smem_set) {
        cudaFuncSetAttribute(k_fused, cudaFuncAttributeMaxDynamicSharedMemorySize, DYN_SMEM);
        cudaFuncSetAttribute(k_sort,  cudaFuncAttributeMaxDynamicSharedMemorySize, SORT_SMEM);
        smem_set = 1;
    }

    int nmain = (NTILE * (NTILE + 1)) / 2;
    k_sort <<<1, 512, SORT_SMEM>>>(labels);                          // 0
    k_prep <<<Nn / 8, 256>>>(X);                                     // 1
    k_fused<<<NANCH + nmain, 256, DYN_SMEM>>>((float*)d_out);        // 2 (ncu: idx 5 = replay-2's k_fused)
}

// round 15
// speedup vs baseline: 1.2384x; 1.2384x over previous
#include <cuda_runtime.h>
#include <cuda_bf16.h>
#include <math.h>
#include <cstdint>

#define Nn 8192
#define Dd 128
#define Cc 512
#define ALPHA 0.2f
#define ALPHA_BITS 0x3E4CCCCDu   // bit pattern of 0.2f
#define NTILE 64
#define KSRC 256             // buf row: [hi(128), lo(128)]
#define BK 64
#define KCHUNKS 4
#define NSTAGE 3
#define TILEB 16384          // 128 rows * 64 bf16 * 2B
#define DYN_SMEM (1024 + 2 * NSTAGE * TILEB)
#define NANCH 256            // anchor blocks (64 j-tiles x 4 label-tiles)
#define NSEG 32
#define SEGSZ 256
#define SCAN_SMEM (NSEG * Cc * 4)

// ---------------- device scratch ----------------
__device__ float  g_sq [Nn];
__device__ float  g_ap [Nn];
__device__ int    g_lab[Nn];
__device__ int    g_perm[Nn];
__device__ int    g_pos [Nn];
__device__ int    g_offset[Cc + 1];
__device__ int    g_part[NSEG * Cc];    // [seg][label] counts -> seg-excl offsets
__device__ __nv_bfloat16 g_Abuf[(size_t)Nn * KSRC];
__device__ __nv_bfloat16 g_Anc [(size_t)Cc * KSRC];
__device__ float  g_sqA[Cc];
__device__ double g_acc;

// ---------------- PTX helpers ----------------
__device__ __forceinline__ uint32_t smem_u32(const void* p) {
    uint32_t a;
    asm("{ .reg .u64 t; cvta.to.shared.u64 t, %1; cvt.u32.u64 %0, t; }" : "=r"(a) : "l"(p));
    return a;
}
__device__ __forceinline__ void cpasync16(uint32_t s, const void* g) {
    asm volatile("cp.async.cg.shared.global [%0], [%1], 16;" :: "r"(s), "l"(g));
}
__device__ __forceinline__ void cp_commit() {
    asm volatile("cp.async.commit_group;" ::: "memory");
}
template <int N>
__device__ __forceinline__ void cp_wait() {
    asm volatile("cp.async.wait_group %0;" :: "n"(N) : "memory");
}
__device__ __forceinline__ void ldm_x4(uint32_t& r0, uint32_t& r1, uint32_t& r2,
                                       uint32_t& r3, uint32_t addr) {
    asm volatile("ldmatrix.sync.aligned.m8n8.x4.shared.b16 {%0,%1,%2,%3}, [%4];"
                 : "=r"(r0), "=r"(r1), "=r"(r2), "=r"(r3) : "r"(addr));
}
__device__ __forceinline__ void mma16816(float* c, uint32_t a0, uint32_t a1,
                                         uint32_t a2, uint32_t a3,
                                         uint32_t b0, uint32_t b1) {
    asm volatile(
        "mma.sync.aligned.m16n8k16.row.col.f32.bf16.bf16.f32 "
        "{%0,%1,%2,%3}, {%4,%5,%6,%7}, {%8,%9}, {%0,%1,%2,%3};"
        : "+f"(c[0]), "+f"(c[1]), "+f"(c[2]), "+f"(c[3])
        : "r"(a0), "r"(a1), "r"(a2), "r"(a3), "r"(b0), "r"(b1));
}
// single-ISETP hinge: contribute t iff 0 < t < ALPHA (t==0 adds 0.0, harmless)
__device__ __forceinline__ void hinge(float t, float& s) {
    if (__float_as_uint(t) < ALPHA_BITS) s += t;
}

// ---------------- sort phase 1: per-segment histogram -----------------------
__global__ void __launch_bounds__(256) k_hist(const int* __restrict__ labels) {
    __shared__ int cnt[Cc];
    int tid = threadIdx.x, seg = blockIdx.x;
    cnt[tid] = 0; cnt[tid + 256] = 0;
    if (seg == 0 && tid == 0) g_acc = 0.0;
    __syncthreads();
    int l = labels[seg * SEGSZ + tid];
    atomicAdd(&cnt[l], 1);
    __syncthreads();
    g_part[seg * Cc + tid]       = cnt[tid];
    g_part[seg * Cc + tid + 256] = cnt[tid + 256];
}

// ---------------- sort phase 2: scan (1 block, smem-resident) ---------------
__global__ void __launch_bounds__(512, 1) k_scan() {
    extern __shared__ int sp[];           // [NSEG][Cc]
    __shared__ int wtot[16];
    int tid = threadIdx.x;
    int lane = tid & 31, wrp = tid >> 5;

    for (int q = tid; q < NSEG * Cc; q += 512) sp[q] = g_part[q];
    __syncthreads();

    // per-label exclusive prefix over segments (stride-Cc = conflict-free)
    int run = 0;
#pragma unroll
    for (int s = 0; s < NSEG; s++) {
        int t = sp[s * Cc + tid];
        sp[s * Cc + tid] = run;
        run += t;
    }
    int v = run;

    // inclusive warp-shuffle scan over 512 labels
#pragma unroll
    for (int o = 1; o < 32; o <<= 1) {
        int n = __shfl_up_sync(0xffffffffu, v, o);
        if (lane >= o) v += n;
    }
    if (lane == 31) wtot[wrp] = v;
    __syncthreads();
    if (wrp == 0) {
        int w = (lane < 16) ? wtot[lane] : 0;
#pragma unroll
        for (int o = 1; o < 16; o <<= 1) {
            int n = __shfl_up_sync(0xffffffffu, w, o);
            if (lane >= o) w += n;
        }
        if (lane < 16) wtot[lane] = w;
    }
    __syncthreads();
    int incl = v + (wrp ? wtot[wrp - 1] : 0);
    g_offset[tid + 1] = incl;
    if (tid == 0) g_offset[0] = 0;
    __syncthreads();

    for (int q = tid; q < NSEG * Cc; q += 512) g_part[q] = sp[q];
}

// ---------------- sort phase 3: stable scatter ------------------------------
__global__ void __launch_bounds__(256) k_scatter(const int* __restrict__ labels) {
    __shared__ int slab[SEGSZ];
    __shared__ int soff[Cc];
    int tid = threadIdx.x, seg = blockIdx.x;
    slab[tid] = labels[seg * SEGSZ + tid];
    soff[tid]       = g_offset[tid]       + g_part[seg * Cc + tid];
    soff[tid + 256] = g_offset[tid + 256] + g_part[seg * Cc + tid + 256];
    __syncthreads();

    int l = slab[tid];
    int r = 0;
    for (int p = 0; p < tid; p++) r += (slab[p] == l);   // broadcast reads
    int pos = soff[l] + r;
    g_perm[pos] = seg * SEGSZ + tid;
    g_lab[pos]  = l;
}

// ---------------- prep: warp-per-row gather/split/norms/ap ------------------
__global__ void __launch_bounds__(256, 8) k_prep(const float* __restrict__ X) {
    int wid = threadIdx.x >> 5, lane = threadIdx.x & 31;
    int row = blockIdx.x * 8 + wid;
    int l = g_lab[row];
    int a = g_offset[l];
    int orig  = g_perm[row];
    int origA = g_perm[a];

    float4 v  = ((const float4*)(X + (size_t)orig  * Dd))[lane];
    float4 va = ((const float4*)(X + (size_t)origA * Dd))[lane];

    __nv_bfloat162 h01, h23, l01, l23;
    h01.x = __float2bfloat16(v.x); h01.y = __float2bfloat16(v.y);
    h23.x = __float2bfloat16(v.z); h23.y = __float2bfloat16(v.w);
    l01.x = __float2bfloat16(v.x - __bfloat162float(h01.x));
    l01.y = __float2bfloat16(v.y - __bfloat162float(h01.y));
    l23.x = __float2bfloat16(v.z - __bfloat162float(h23.x));
    l23.y = __float2bfloat16(v.w - __bfloat162float(h23.y));
    uint2 hi2 = make_uint2(*(uint32_t*)&h01, *(uint32_t*)&h23);
    uint2 lo2 = make_uint2(*(uint32_t*)&l01, *(uint32_t*)&l23);
    size_t b = (size_t)row * KSRC;
    *(uint2*)(g_Abuf + b + lane * 4)       = hi2;
    *(uint2*)(g_Abuf + b + 128 + lane * 4) = lo2;
    if (row == a) {
        size_t ba = (size_t)l * KSRC;
        *(uint2*)(g_Anc + ba + lane * 4)       = hi2;
        *(uint2*)(g_Anc + ba + 128 + lane * 4) = lo2;
    }

    float s1 = v.x * v.x + v.y * v.y + v.z * v.z + v.w * v.w;
    float s2 = va.x * va.x + va.y * va.y + va.z * va.z + va.w * va.w;
    float s3 = v.x * va.x + v.y * va.y + v.z * va.z + v.w * va.w;
#pragma unroll
    for (int o = 16; o > 0; o >>= 1) {
        s1 += __shfl_down_sync(0xffffffffu, s1, o);
        s2 += __shfl_down_sync(0xffffffffu, s2, o);
        s3 += __shfl_down_sync(0xffffffffu, s3, o);
    }
    if (lane == 0) {
        g_sq[row]  = s1;
        g_ap[row]  = s2 + s1 - 2.0f * s3;
        g_pos[row] = (row != a) ? 1 : 0;
        if (row == a) g_sqA[l] = s1;
    }
}

// ---------------- fused: anchor blocks (0..255) + main tiles (256..2335) ----
__global__ void __launch_bounds__(256, 2) k_fused() {
    extern __shared__ char dynsm[];
    __shared__ float sSqI[128], sSqJ[128], sApIA[128], sApJA[128];
    __shared__ int   sLabI[128], sLabJ[128];
    __shared__ int   sOff[129];
    __shared__ float sSqA[128];
    __shared__ float warpsum[8];

    int tid = threadIdx.x;
    int wid = tid >> 5, lane = tid & 31;
    int wm = wid & 3, wn = wid >> 2;
    int lrow = lane & 15, lkh = lane >> 4;
    int tg = lane & 3, gID = lane >> 2;

    int bid = blockIdx.x;
    int is_anch = (bid < NANCH);
    int i0 = 0, j0, l0 = 0, by = 0, bx = 0, offdiag = 0;
    const __nv_bfloat16 *aSrc, *bSrc;

    if (is_anch) {
        j0 = (bid & 63) * 128;
        l0 = (bid >> 6) * 128;
        aSrc = g_Anc  + (size_t)l0 * KSRC;
        bSrc = g_Abuf + (size_t)j0 * KSRC;
    } else {
        int t = bid - NANCH;
        by = (int)(0.5f * (129.0f - sqrtf(16641.0f - 8.0f * (float)t)));
        while ((by + 1) * NTILE - (((by + 1) * by) >> 1) <= t) by++;
        while (by * NTILE - ((by * (by - 1)) >> 1) > t) by--;
        bx = by + t - (by * NTILE - ((by * (by - 1)) >> 1));
        i0 = by * 128; j0 = bx * 128;
        offdiag = (bx != by);
        aSrc = g_Abuf + (size_t)i0 * KSRC;
        bSrc = g_Abuf + (size_t)j0 * KSRC;
    }

    uint32_t dbase = smem_u32(dynsm);
    uint32_t smBase = (dbase + 1023u) & ~1023u;

    if (is_anch) {
        if (tid < 129) sOff[tid] = g_offset[l0 + tid];
        if (tid < 128) sSqJ[tid] = g_sq[j0 + tid];
        else if (tid >= 128) sSqA[tid - 128] = g_sqA[l0 + tid - 128];
    } else {
        if (tid < 128) {
            int i = i0 + tid;
            sSqI[tid]  = g_sq[i];
            sLabI[tid] = g_lab[i];
            sApIA[tid] = g_pos[i] ? (g_ap[i] + ALPHA) : -1e30f;
        } else {
            int tt2 = tid - 128;
            int j = j0 + tt2;
            sSqJ[tt2]  = g_sq[j];
            sLabJ[tt2] = g_lab[j];
            sApJA[tt2] = (offdiag && g_pos[j]) ? (g_ap[j] + ALPHA) : -1e30f;
        }
    }

    float acc[2][8][4];
#pragma unroll
    for (int a = 0; a < 2; a++)
#pragma unroll
        for (int b = 0; b < 8; b++)
#pragma unroll
            for (int e = 0; e < 4; e++) acc[a][b][e] = 0.0f;

    int lr[4], ls[4];
    uint32_t loff[4];
#pragma unroll
    for (int p = 0; p < 4; p++) {
        int q = tid + p * 256;
        lr[p] = q >> 3;
        ls[p] = q & 7;
        loff[p] = (uint32_t)lr[p] * 128u + (((uint32_t)ls[p] * 16u) ^ (((uint32_t)lr[p] & 7u) << 4));
    }

    // prefetch chunks 0,1
#pragma unroll
    for (int c0 = 0; c0 < NSTAGE - 1; c0++) {
        uint32_t sA = smBase + (uint32_t)c0 * 2u * TILEB;
        uint32_t sB = sA + TILEB;
        int kk = c0 * BK;
#pragma unroll
        for (int p = 0; p < 4; p++) {
            cpasync16(sA + loff[p], aSrc + (size_t)lr[p] * KSRC + kk + ls[p] * 8);
            cpasync16(sB + loff[p], bSrc + (size_t)lr[p] * KSRC + kk + ls[p] * 8);
        }
        cp_commit();
    }

    int arow = wm * 32 + lrow;
    uint32_t aOff = (uint32_t)arow * 128u;
    uint32_t aXor = ((uint32_t)arow & 7u) << 4;

    // single-sync pipeline: [cp_wait][sync][issue c+2][consume c]
    for (int c = 0; c < KCHUNKS; c++) {
        if (c < KCHUNKS - 1) cp_wait<NSTAGE - 2>();
        else                 cp_wait<0>();
        __syncthreads();
        if (c + NSTAGE - 1 < KCHUNKS) {
            int cn = c + NSTAGE - 1;
            int kk = cn * BK;
            uint32_t sA = smBase + (uint32_t)(cn % NSTAGE) * 2u * TILEB;
            uint32_t sB = sA + TILEB;
#pragma unroll
            for (int p = 0; p < 4; p++) {
                cpasync16(sA + loff[p], aSrc + (size_t)lr[p] * KSRC + kk + ls[p] * 8);
                cpasync16(sB + loff[p], bSrc + (size_t)lr[p] * KSRC + kk + ls[p] * 8);
            }
            cp_commit();
        }

        uint32_t aB = smBase + (uint32_t)(c % NSTAGE) * 2u * TILEB;
        uint32_t bB = aB + TILEB;
#pragma unroll
        for (int ks = 0; ks < 4; ks++) {
            uint32_t koff = (uint32_t)(ks * 32 + lkh * 16);
            uint32_t a0[2], a1[2], a2[2], a3[2];
#pragma unroll
            for (int mi = 0; mi < 2; mi++)
                ldm_x4(a0[mi], a1[mi], a2[mi], a3[mi],
                       aB + aOff + (uint32_t)mi * 2048u + (koff ^ aXor));
#pragma unroll
            for (int g2 = 0; g2 < 4; g2++) {
                int brow = wn * 64 + g2 * 16 + lrow;
                uint32_t r0, r1, r2, r3;
                ldm_x4(r0, r1, r2, r3,
                       bB + (uint32_t)brow * 128u + (koff ^ (((uint32_t)brow & 7u) << 4)));
#pragma unroll
                for (int mi = 0; mi < 2; mi++) {
                    mma16816(acc[mi][2 * g2],     a0[mi], a1[mi], a2[mi], a3[mi], r0, r2);
                    mma16816(acc[mi][2 * g2 + 1], a0[mi], a1[mi], a2[mi], a3[mi], r1, r3);
                }
            }
        }
    }

    float csum0 = 0.0f, csum1 = 0.0f;

    if (is_anch) {
        // all warps must finish reading tile smem before reuse for sap
        __syncthreads();
        float* sap = (float*)dynsm;
        int apbase = sOff[0];
        int apcnt  = sOff[128] - apbase;
        for (int q = tid; q < apcnt; q += 256) sap[q] = g_ap[apbase + q];
        __syncthreads();

#pragma unroll
        for (int ridx = 0; ridx < 4; ridx++) {
            int mi = ridx >> 1, e2 = ridx & 1;
            int row = wm * 32 + mi * 16 + gID + e2 * 8;
            int s0 = sOff[row], s1 = sOff[row + 1];
            int m = s1 - s0 - 1;
            if (m > 0) {
                float nsqaA = ALPHA - sSqA[row];
                float negD[16];
#pragma unroll
                for (int ni = 0; ni < 8; ni++)
#pragma unroll
                    for (int e1 = 0; e1 < 2; e1++) {
                        int col = wn * 64 + ni * 8 + 2 * tg + e1;
                        int j = j0 + col;
                        float nd = fmaf(2.0f, acc[mi][ni][e2 * 2 + e1], nsqaA - sSqJ[col]);
                        negD[ni * 2 + e1] = (j >= s0 && j < s1) ? -1e30f : nd;
                    }
                int qb = s0 - apbase + 1;
                for (int q = 0; q < m; q++) {
                    float apq = sap[qb + q];
#pragma unroll
                    for (int c16 = 0; c16 < 16; c16 += 2) {
                        hinge(apq + negD[c16],     csum0);
                        hinge(apq + negD[c16 + 1], csum1);
                    }
                }
            }
        }
    } else {
        float rSq[4], rC[4];
        int   rLab[4];
#pragma unroll
        for (int mi = 0; mi < 2; mi++)
#pragma unroll
            for (int e2 = 0; e2 < 2; e2++) {
                int ridx = mi * 2 + e2;
                int row = wm * 32 + mi * 16 + gID + e2 * 8;
                rSq[ridx]  = sSqI[row];
                rLab[ridx] = sLabI[row];
                rC[ridx]   = sApIA[row] - rSq[ridx];
            }

        int collide = (by == bx) || (sLabI[127] == sLabJ[0]);

        if (!collide) {
#pragma unroll
            for (int ni = 0; ni < 8; ni++)
#pragma unroll
                for (int e1 = 0; e1 < 2; e1++) {
                    int col = wn * 64 + ni * 8 + 2 * tg + e1;
                    float cSq = sSqJ[col];
                    float cC  = sApJA[col] - cSq;
#pragma unroll
                    for (int mi = 0; mi < 2; mi++)
#pragma unroll
                        for (int e2 = 0; e2 < 2; e2++) {
                            int ridx = mi * 2 + e2;
                            float av = acc[mi][ni][e2 * 2 + e1];
                            hinge(fmaf(2.0f, av, rC[ridx] - cSq), csum0);
                            hinge(fmaf(2.0f, av, cC - rSq[ridx]), csum1);
                        }
                }
        } else {
#pragma unroll
            for (int ni = 0; ni < 8; ni++)
#pragma unroll
                for (int e1 = 0; e1 < 2; e1++) {
                    int col = wn * 64 + ni * 8 + 2 * tg + e1;
                    float cSq = sSqJ[col];
                    float cC  = sApJA[col] - cSq;
                    int   cLab = sLabJ[col];
#pragma unroll
                    for (int mi = 0; mi < 2; mi++)
#pragma unroll
                        for (int e2 = 0; e2 < 2; e2++) {
                            int ridx = mi * 2 + e2;
                            if (rLab[ridx] == cLab) continue;
                            float av = acc[mi][ni][e2 * 2 + e1];
                            hinge(fmaf(2.0f, av, rC[ridx] - cSq), csum0);
                            hinge(fmaf(2.0f, av, cC - rSq[ridx]), csum1);
                        }
                }
        }
    }

    float csum = csum0 + csum1;
#pragma unroll
    for (int o = 16; o > 0; o >>= 1) csum += __shfl_down_sync(0xffffffffu, csum, o);
    if (lane == 0) warpsum[wid] = csum;
    __syncthreads();
    if (wid == 0) {
        float tt2 = (lane < 8) ? warpsum[lane] : 0.0f;
#pragma unroll
        for (int o = 4; o > 0; o >>= 1) tt2 += __shfl_down_sync(0xffffffffu, tt2, o);
        if (lane == 0) atomicAdd(&g_acc, (double)tt2);
    }
}

__global__ void k_out(float* __restrict__ out) {
    if (threadIdx.x == 0) out[0] = (float)g_acc;
}

// ---------------- launch ----------------
extern "C" void kernel_launch(void* const* d_in, const int* in_sizes, int n_in,
                              void* d_out, int out_size) {
    const float* X      = (const float*)d_in[0];
    const int*   labels = (const int*)d_in[1];

    static int smem_set = 0;
    if (!smem_set) {
        cudaFuncSetAttribute(k_fused, cudaFuncAttributeMaxDynamicSharedMemorySize, DYN_SMEM);
        cudaFuncSetAttribute(k_scan,  cudaFuncAttributeMaxDynamicSharedMemorySize, SCAN_SMEM);
        smem_set = 1;
    }

    int nmain = (NTILE * (NTILE + 1)) / 2;
    k_hist   <<<NSEG, 256>>>(labels);                    // 0
    k_scan   <<<1, 512, SCAN_SMEM>>>();                  // 1
    k_scatter<<<NSEG, 256>>>(labels);                    // 2
    k_prep   <<<Nn / 8, 256>>>(X);                       // 3
    k_fused  <<<NANCH + nmain, 256, DYN_SMEM>>>();       // 4
    k_out    <<<1, 32>>>((float*)d_out);                 // 5
}

// round 16
// speedup vs baseline: 1.2571x; 1.0151x over previous
#include <cuda_runtime.h>
#include <cuda_bf16.h>
#include <math.h>
#include <cstdint>

#define Nn 8192
#define Dd 128
#define Cc 512
#define ALPHA 0.2f
#define ALPHA_BITS 0x3E4CCCCDu   // bit pattern of 0.2f
#define NTILE 64
#define KSRC 256             // buf row: [hi(128), lo(128)]
#define BK 64
#define KCHUNKS 4
#define NSTAGE 3
#define TILEB 16384          // 128 rows * 64 bf16 * 2B
#define DYN_SMEM (1024 + 2 * NSTAGE * TILEB)
#define NANCH 256            // anchor blocks (64 j-tiles x 4 label-tiles)
#define NSEG 32
#define SEGSZ 256
#define SCAT_SMEM (NSEG * Cc * 4)

// ---------------- device scratch ----------------
__device__ float  g_sq [Nn];
__device__ float  g_ap [Nn];
__device__ int    g_lab[Nn];
__device__ int    g_perm[Nn];
__device__ int    g_pos [Nn];
__device__ int    g_offset[Cc + 1];
__device__ int    g_part[NSEG * Cc];    // [seg][label] counts
__device__ __nv_bfloat16 g_Abuf[(size_t)Nn * KSRC];
__device__ __nv_bfloat16 g_Anc [(size_t)Cc * KSRC];
__device__ float  g_sqA[Cc];
__device__ double g_acc;

// ---------------- PTX helpers ----------------
__device__ __forceinline__ uint32_t smem_u32(const void* p) {
    uint32_t a;
    asm("{ .reg .u64 t; cvta.to.shared.u64 t, %1; cvt.u32.u64 %0, t; }" : "=r"(a) : "l"(p));
    return a;
}
__device__ __forceinline__ void cpasync16(uint32_t s, const void* g) {
    asm volatile("cp.async.cg.shared.global [%0], [%1], 16;" :: "r"(s), "l"(g));
}
__device__ __forceinline__ void cp_commit() {
    asm volatile("cp.async.commit_group;" ::: "memory");
}
template <int N>
__device__ __forceinline__ void cp_wait() {
    asm volatile("cp.async.wait_group %0;" :: "n"(N) : "memory");
}
__device__ __forceinline__ void ldm_x4(uint32_t& r0, uint32_t& r1, uint32_t& r2,
                                       uint32_t& r3, uint32_t addr) {
    asm volatile("ldmatrix.sync.aligned.m8n8.x4.shared.b16 {%0,%1,%2,%3}, [%4];"
                 : "=r"(r0), "=r"(r1), "=r"(r2), "=r"(r3) : "r"(addr));
}
__device__ __forceinline__ void mma16816(float* c, uint32_t a0, uint32_t a1,
                                         uint32_t a2, uint32_t a3,
                                         uint32_t b0, uint32_t b1) {
    asm volatile(
        "mma.sync.aligned.m16n8k16.row.col.f32.bf16.bf16.f32 "
        "{%0,%1,%2,%3}, {%4,%5,%6,%7}, {%8,%9}, {%0,%1,%2,%3};"
        : "+f"(c[0]), "+f"(c[1]), "+f"(c[2]), "+f"(c[3])
        : "r"(a0), "r"(a1), "r"(a2), "r"(a3), "r"(b0), "r"(b1));
}
// single-ISETP hinge: contribute t iff 0 < t < ALPHA (t==0 adds 0.0, harmless)
__device__ __forceinline__ void hinge(float t, float& s) {
    if (__float_as_uint(t) < ALPHA_BITS) s += t;
}

// ---------------- sort phase 1: per-segment histogram -----------------------
__global__ void __launch_bounds__(256) k_hist(const int* __restrict__ labels) {
    __shared__ int cnt[Cc];
    int tid = threadIdx.x, seg = blockIdx.x;
    cnt[tid] = 0; cnt[tid + 256] = 0;
    if (seg == 0 && tid == 0) g_acc = 0.0;
    __syncthreads();
    int l = labels[seg * SEGSZ + tid];
    atomicAdd(&cnt[l], 1);
    __syncthreads();
    g_part[seg * Cc + tid]       = cnt[tid];
    g_part[seg * Cc + tid + 256] = cnt[tid + 256];
}

// ---------------- sort phase 2: scatter w/ redundant per-block scan ---------
__global__ void __launch_bounds__(512, 1) k_scatter(const int* __restrict__ labels) {
    extern __shared__ int sp[];           // [NSEG][Cc]
    __shared__ int slab[SEGSZ];
    __shared__ int soff[Cc];
    __shared__ int wtot[16];
    int tid = threadIdx.x, seg = blockIdx.x;
    int lane = tid & 31, wrp = tid >> 5;

    for (int q = tid; q < NSEG * Cc; q += 512) sp[q] = g_part[q];
    if (tid < SEGSZ) slab[tid] = labels[seg * SEGSZ + tid];
    __syncthreads();

    // thread tid = label tid: sum counts over segments, remember prefix at own seg
    int run = 0, mine = 0;
#pragma unroll
    for (int s = 0; s < NSEG; s++) {
        if (s == seg) mine = run;
        run += sp[s * Cc + tid];
    }
    int v = run;  // total count for this label

    // inclusive warp-shuffle scan over 512 labels
#pragma unroll
    for (int o = 1; o < 32; o <<= 1) {
        int n = __shfl_up_sync(0xffffffffu, v, o);
        if (lane >= o) v += n;
    }
    if (lane == 31) wtot[wrp] = v;
    __syncthreads();
    if (wrp == 0) {
        int w = (lane < 16) ? wtot[lane] : 0;
#pragma unroll
        for (int o = 1; o < 16; o <<= 1) {
            int n = __shfl_up_sync(0xffffffffu, w, o);
            if (lane >= o) w += n;
        }
        if (lane < 16) wtot[lane] = w;
    }
    __syncthreads();
    int incl = v + (wrp ? wtot[wrp - 1] : 0);
    soff[tid] = (incl - run) + mine;      // global excl + seg-prefix for this label
    if (seg == 0) {
        g_offset[tid + 1] = incl;
        if (tid == 0) g_offset[0] = 0;
    }
    __syncthreads();

    if (tid < SEGSZ) {
        int l = slab[tid];
        int r = 0;
        for (int p = 0; p < tid; p++) r += (slab[p] == l);   // broadcast reads
        int pos = soff[l] + r;
        g_perm[pos] = seg * SEGSZ + tid;
        g_lab[pos]  = l;
    }
}

// ---------------- prep: 2 rows per warp, gather/split/norms/ap --------------
__global__ void __launch_bounds__(256, 8) k_prep(const float* __restrict__ X) {
    int wid = threadIdx.x >> 5, lane = threadIdx.x & 31;
    int row0 = blockIdx.x * 16 + wid * 2;

#pragma unroll
    for (int r = 0; r < 2; r++) {
        int row = row0 + r;
        int l = g_lab[row];
        int a = g_offset[l];
        int orig  = g_perm[row];
        int origA = g_perm[a];

        float4 v  = ((const float4*)(X + (size_t)orig  * Dd))[lane];
        float4 va = ((const float4*)(X + (size_t)origA * Dd))[lane];

        __nv_bfloat162 h01, h23, l01, l23;
        h01.x = __float2bfloat16(v.x); h01.y = __float2bfloat16(v.y);
        h23.x = __float2bfloat16(v.z); h23.y = __float2bfloat16(v.w);
        l01.x = __float2bfloat16(v.x - __bfloat162float(h01.x));
        l01.y = __float2bfloat16(v.y - __bfloat162float(h01.y));
        l23.x = __float2bfloat16(v.z - __bfloat162float(h23.x));
        l23.y = __float2bfloat16(v.w - __bfloat162float(h23.y));
        uint2 hi2 = make_uint2(*(uint32_t*)&h01, *(uint32_t*)&h23);
        uint2 lo2 = make_uint2(*(uint32_t*)&l01, *(uint32_t*)&l23);
        size_t b = (size_t)row * KSRC;
        *(uint2*)(g_Abuf + b + lane * 4)       = hi2;
        *(uint2*)(g_Abuf + b + 128 + lane * 4) = lo2;
        if (row == a) {
            size_t ba = (size_t)l * KSRC;
            *(uint2*)(g_Anc + ba + lane * 4)       = hi2;
            *(uint2*)(g_Anc + ba + 128 + lane * 4) = lo2;
        }

        float s1 = v.x * v.x + v.y * v.y + v.z * v.z + v.w * v.w;
        float s2 = va.x * va.x + va.y * va.y + va.z * va.z + va.w * va.w;
        float s3 = v.x * va.x + v.y * va.y + v.z * va.z + v.w * va.w;
#pragma unroll
        for (int o = 16; o > 0; o >>= 1) {
            s1 += __shfl_down_sync(0xffffffffu, s1, o);
            s2 += __shfl_down_sync(0xffffffffu, s2, o);
            s3 += __shfl_down_sync(0xffffffffu, s3, o);
        }
        if (lane == 0) {
            g_sq[row]  = s1;
            g_ap[row]  = s2 + s1 - 2.0f * s3;
            g_pos[row] = (row != a) ? 1 : 0;
            if (row == a) g_sqA[l] = s1;
        }
    }
}

// ---------------- fused: anchor blocks (0..255) + main tiles (256..2335) ----
__global__ void __launch_bounds__(256, 2) k_fused() {
    extern __shared__ char dynsm[];
    __shared__ float sSqI[128], sSqJ[128], sApIA[128], sApJA[128];
    __shared__ int   sLabI[128], sLabJ[128];
    __shared__ int   sOff[129];
    __shared__ float sSqA[128];
    __shared__ float warpsum[8];

    int tid = threadIdx.x;
    int wid = tid >> 5, lane = tid & 31;
    int wm = wid & 3, wn = wid >> 2;
    int lrow = lane & 15, lkh = lane >> 4;
    int tg = lane & 3, gID = lane >> 2;

    int bid = blockIdx.x;
    int is_anch = (bid < NANCH);
    int i0 = 0, j0, l0 = 0, by = 0, bx = 0, offdiag = 0;
    const __nv_bfloat16 *aSrc, *bSrc;

    if (is_anch) {
        j0 = (bid & 63) * 128;
        l0 = (bid >> 6) * 128;
        aSrc = g_Anc  + (size_t)l0 * KSRC;
        bSrc = g_Abuf + (size_t)j0 * KSRC;
    } else {
        int t = bid - NANCH;
        by = (int)(0.5f * (129.0f - sqrtf(16641.0f - 8.0f * (float)t)));
        while ((by + 1) * NTILE - (((by + 1) * by) >> 1) <= t) by++;
        while (by * NTILE - ((by * (by - 1)) >> 1) > t) by--;
        bx = by + t - (by * NTILE - ((by * (by - 1)) >> 1));
        i0 = by * 128; j0 = bx * 128;
        offdiag = (bx != by);
        aSrc = g_Abuf + (size_t)i0 * KSRC;
        bSrc = g_Abuf + (size_t)j0 * KSRC;
    }

    uint32_t dbase = smem_u32(dynsm);
    uint32_t smBase = (dbase + 1023u) & ~1023u;

    if (is_anch) {
        if (tid < 129) sOff[tid] = g_offset[l0 + tid];
        if (tid < 128) sSqJ[tid] = g_sq[j0 + tid];
        else if (tid >= 128) sSqA[tid - 128] = g_sqA[l0 + tid - 128];
    } else {
        if (tid < 128) {
            int i = i0 + tid;
            sSqI[tid]  = g_sq[i];
            sLabI[tid] = g_lab[i];
            sApIA[tid] = g_pos[i] ? (g_ap[i] + ALPHA) : -1e30f;
        } else {
            int tt2 = tid - 128;
            int j = j0 + tt2;
            sSqJ[tt2]  = g_sq[j];
            sLabJ[tt2] = g_lab[j];
            sApJA[tt2] = (offdiag && g_pos[j]) ? (g_ap[j] + ALPHA) : -1e30f;
        }
    }

    float acc[2][8][4];
#pragma unroll
    for (int a = 0; a < 2; a++)
#pragma unroll
        for (int b = 0; b < 8; b++)
#pragma unroll
            for (int e = 0; e < 4; e++) acc[a][b][e] = 0.0f;

    int lr[4], ls[4];
    uint32_t loff[4];
#pragma unroll
    for (int p = 0; p < 4; p++) {
        int q = tid + p * 256;
        lr[p] = q >> 3;
        ls[p] = q & 7;
        loff[p] = (uint32_t)lr[p] * 128u + (((uint32_t)ls[p] * 16u) ^ (((uint32_t)lr[p] & 7u) << 4));
    }

    // prefetch chunks 0,1
#pragma unroll
    for (int c0 = 0; c0 < NSTAGE - 1; c0++) {
        uint32_t sA = smBase + (uint32_t)c0 * 2u * TILEB;
        uint32_t sB = sA + TILEB;
        int kk = c0 * BK;
#pragma unroll
        for (int p = 0; p < 4; p++) {
            cpasync16(sA + loff[p], aSrc + (size_t)lr[p] * KSRC + kk + ls[p] * 8);
            cpasync16(sB + loff[p], bSrc + (size_t)lr[p] * KSRC + kk + ls[p] * 8);
        }
        cp_commit();
    }

    int arow = wm * 32 + lrow;
    uint32_t aOff = (uint32_t)arow * 128u;
    uint32_t aXor = ((uint32_t)arow & 7u) << 4;

    // single-sync pipeline: [cp_wait][sync][issue c+2][consume c]
    for (int c = 0; c < KCHUNKS; c++) {
        if (c < KCHUNKS - 1) cp_wait<NSTAGE - 2>();
        else                 cp_wait<0>();
        __syncthreads();
        if (c + NSTAGE - 1 < KCHUNKS) {
            int cn = c + NSTAGE - 1;
            int kk = cn * BK;
            uint32_t sA = smBase + (uint32_t)(cn % NSTAGE) * 2u * TILEB;
            uint32_t sB = sA + TILEB;
#pragma unroll
            for (int p = 0; p < 4; p++) {
                cpasync16(sA + loff[p], aSrc + (size_t)lr[p] * KSRC + kk + ls[p] * 8);
                cpasync16(sB + loff[p], bSrc + (size_t)lr[p] * KSRC + kk + ls[p] * 8);
            }
            cp_commit();
        }

        uint32_t aB = smBase + (uint32_t)(c % NSTAGE) * 2u * TILEB;
        uint32_t bB = aB + TILEB;
#pragma unroll
        for (int ks = 0; ks < 4; ks++) {
            uint32_t koff = (uint32_t)(ks * 32 + lkh * 16);
            uint32_t a0[2], a1[2], a2[2], a3[2];
#pragma unroll
            for (int mi = 0; mi < 2; mi++)
                ldm_x4(a0[mi], a1[mi], a2[mi], a3[mi],
                       aB + aOff + (uint32_t)mi * 2048u + (koff ^ aXor));
#pragma unroll
            for (int g2 = 0; g2 < 4; g2++) {
                int brow = wn * 64 + g2 * 16 + lrow;
                uint32_t r0, r1, r2, r3;
                ldm_x4(r0, r1, r2, r3,
                       bB + (uint32_t)brow * 128u + (koff ^ (((uint32_t)brow & 7u) << 4)));
#pragma unroll
                for (int mi = 0; mi < 2; mi++) {
                    mma16816(acc[mi][2 * g2],     a0[mi], a1[mi], a2[mi], a3[mi], r0, r2);
                    mma16816(acc[mi][2 * g2 + 1], a0[mi], a1[mi], a2[mi], a3[mi], r1, r3);
                }
            }
        }
    }

    float csum0 = 0.0f, csum1 = 0.0f;

    if (is_anch) {
        // all warps must finish reading tile smem before reuse for sap
        __syncthreads();
        float* sap = (float*)dynsm;
        int apbase = sOff[0];
        int apcnt  = sOff[128] - apbase;
        for (int q = tid; q < apcnt; q += 256) sap[q] = g_ap[apbase + q];
        __syncthreads();

#pragma unroll
        for (int ridx = 0; ridx < 4; ridx++) {
            int mi = ridx >> 1, e2 = ridx & 1;
            int row = wm * 32 + mi * 16 + gID + e2 * 8;
            int s0 = sOff[row], s1 = sOff[row + 1];
            int m = s1 - s0 - 1;
            if (m > 0) {
                float nsqaA = ALPHA - sSqA[row];
                float negD[16];
#pragma unroll
                for (int ni = 0; ni < 8; ni++)
#pragma unroll
                    for (int e1 = 0; e1 < 2; e1++) {
                        int col = wn * 64 + ni * 8 + 2 * tg + e1;
                        int j = j0 + col;
                        float nd = fmaf(2.0f, acc[mi][ni][e2 * 2 + e1], nsqaA - sSqJ[col]);
                        negD[ni * 2 + e1] = (j >= s0 && j < s1) ? -1e30f : nd;
                    }
                int qb = s0 - apbase + 1;
                for (int q = 0; q < m; q++) {
                    float apq = sap[qb + q];
#pragma unroll
                    for (int c16 = 0; c16 < 16; c16 += 2) {
                        hinge(apq + negD[c16],     csum0);
                        hinge(apq + negD[c16 + 1], csum1);
                    }
                }
            }
        }
    } else {
        float rSq[4], rC[4];
        int   rLab[4];
#pragma unroll
        for (int mi = 0; mi < 2; mi++)
#pragma unroll
            for (int e2 = 0; e2 < 2; e2++) {
                int ridx = mi * 2 + e2;
                int row = wm * 32 + mi * 16 + gID + e2 * 8;
                rSq[ridx]  = sSqI[row];
                rLab[ridx] = sLabI[row];
                rC[ridx]   = sApIA[row] - rSq[ridx];
            }

        int collide = (by == bx) || (sLabI[127] == sLabJ[0]);

        if (!collide) {
#pragma unroll
            for (int ni = 0; ni < 8; ni++)
#pragma unroll
                for (int e1 = 0; e1 < 2; e1++) {
                    int col = wn * 64 + ni * 8 + 2 * tg + e1;
                    float cSq = sSqJ[col];
                    float cC  = sApJA[col] - cSq;
#pragma unroll
                    for (int mi = 0; mi < 2; mi++)
#pragma unroll
                        for (int e2 = 0; e2 < 2; e2++) {
                            int ridx = mi * 2 + e2;
                            float av = acc[mi][ni][e2 * 2 + e1];
                            hinge(fmaf(2.0f, av, rC[ridx] - cSq), csum0);
                            hinge(fmaf(2.0f, av, cC - rSq[ridx]), csum1);
                        }
                }
        } else {
#pragma unroll
            for (int ni = 0; ni < 8; ni++)
#pragma unroll
                for (int e1 = 0; e1 < 2; e1++) {
                    int col = wn * 64 + ni * 8 + 2 * tg + e1;
                    float cSq = sSqJ[col];
                    float cC  = sApJA[col] - cSq;
                    int   cLab = sLabJ[col];
#pragma unroll
                    for (int mi = 0; mi < 2; mi++)
#pragma unroll
                        for (int e2 = 0; e2 < 2; e2++) {
                            int ridx = mi * 2 + e2;
                            if (rLab[ridx] == cLab) continue;
                            float av = acc[mi][ni][e2 * 2 + e1];
                            hinge(fmaf(2.0f, av, rC[ridx] - cSq), csum0);
                            hinge(fmaf(2.0f, av, cC - rSq[ridx]), csum1);
                        }
                }
        }
    }

    float csum = csum0 + csum1;
#pragma unroll
    for (int o = 16; o > 0; o >>= 1) csum += __shfl_down_sync(0xffffffffu, csum, o);
    if (lane == 0) warpsum[wid] = csum;
    __syncthreads();
    if (wid == 0) {
        float tt2 = (lane < 8) ? warpsum[lane] : 0.0f;
#pragma unroll
        for (int o = 4; o > 0; o >>= 1) tt2 += __shfl_down_sync(0xffffffffu, tt2, o);
        if (lane == 0) atomicAdd(&g_acc, (double)tt2);
    }
}

__global__ void k_out(float* __restrict__ out) {
    if (threadIdx.x == 0) out[0] = (float)g_acc;
}

// ---------------- launch ----------------
extern "C" void kernel_launch(void* const* d_in, const int* in_sizes, int n_in,
                              void* d_out, int out_size) {
    const float* X      = (const float*)d_in[0];
    const int*   labels = (const int*)d_in[1];

    static int smem_set = 0;
    if (!smem_set) {
        cudaFuncSetAttribute(k_fused,   cudaFuncAttributeMaxDynamicSharedMemorySize, DYN_SMEM);
        cudaFuncSetAttribute(k_scatter, cudaFuncAttributeMaxDynamicSharedMemorySize, SCAT_SMEM);
        smem_set = 1;
    }

    int nmain = (NTILE * (NTILE + 1)) / 2;
    k_hist   <<<NSEG, 256>>>(labels);                    // 0
    k_scatter<<<NSEG, 512, SCAT_SMEM>>>(labels);         // 1
    k_prep   <<<Nn / 16, 256>>>(X);                      // 2
    k_fused  <<<NANCH + nmain, 256, DYN_SMEM>>>();       // 3 (ncu slot)
    k_out    <<<1, 32>>>((float*)d_out);                 // 4
}

// round 17
// speedup vs baseline: 1.2576x; 1.0004x over previous
#include <cuda_runtime.h>
#include <cuda_bf16.h>
#include <math.h>
#include <cstdint>

#define Nn 8192
#define Dd 128
#define Cc 512
#define ALPHA 0.2f
#define ALPHA_BITS 0x3E4CCCCDu   // bit pattern of 0.2f
#define NTILE 64
#define KSRC 256             // buf row: [hi(128), lo(128)]
#define BK 64
#define KCHUNKS 4
#define NSTAGE 3
#define TILEB 16384          // 128 rows * 64 bf16 * 2B
#define DYN_SMEM (1024 + 2 * NSTAGE * TILEB)
#define NANCH 256            // anchor blocks (64 j-tiles x 4 label-tiles)
#define NSEG 32
#define SEGSZ 256
// sort smem: slab 32KB + hist 64KB
#define SORT_SMEM (Nn * 4 + NSEG * Cc * 4)

// ---------------- device scratch ----------------
__device__ float  g_sq [Nn];
__device__ float  g_ap [Nn];
__device__ int    g_lab[Nn];
__device__ int    g_perm[Nn];
__device__ int    g_pos [Nn];
__device__ int    g_offset[Cc + 1];
__device__ __nv_bfloat16 g_Abuf[(size_t)Nn * KSRC];
__device__ __nv_bfloat16 g_Anc [(size_t)Cc * KSRC];
__device__ float  g_sqA[Cc];
__device__ double g_acc;

// ---------------- PTX helpers ----------------
__device__ __forceinline__ uint32_t smem_u32(const void* p) {
    uint32_t a;
    asm("{ .reg .u64 t; cvta.to.shared.u64 t, %1; cvt.u32.u64 %0, t; }" : "=r"(a) : "l"(p));
    return a;
}
__device__ __forceinline__ void cpasync16(uint32_t s, const void* g) {
    asm volatile("cp.async.cg.shared.global [%0], [%1], 16;" :: "r"(s), "l"(g));
}
__device__ __forceinline__ void cp_commit() {
    asm volatile("cp.async.commit_group;" ::: "memory");
}
template <int N>
__device__ __forceinline__ void cp_wait() {
    asm volatile("cp.async.wait_group %0;" :: "n"(N) : "memory");
}
__device__ __forceinline__ void ldm_x4(uint32_t& r0, uint32_t& r1, uint32_t& r2,
                                       uint32_t& r3, uint32_t addr) {
    asm volatile("ldmatrix.sync.aligned.m8n8.x4.shared.b16 {%0,%1,%2,%3}, [%4];"
                 : "=r"(r0), "=r"(r1), "=r"(r2), "=r"(r3) : "r"(addr));
}
__device__ __forceinline__ void mma16816(float* c, uint32_t a0, uint32_t a1,
                                         uint32_t a2, uint32_t a3,
                                         uint32_t b0, uint32_t b1) {
    asm volatile(
        "mma.sync.aligned.m16n8k16.row.col.f32.bf16.bf16.f32 "
        "{%0,%1,%2,%3}, {%4,%5,%6,%7}, {%8,%9}, {%0,%1,%2,%3};"
        : "+f"(c[0]), "+f"(c[1]), "+f"(c[2]), "+f"(c[3])
        : "r"(a0), "r"(a1), "r"(a2), "r"(a3), "r"(b0), "r"(b1));
}
// single-ISETP hinge: contribute t iff 0 < t < ALPHA (t==0 adds 0.0, harmless)
__device__ __forceinline__ void hinge(float t, float& s) {
    if (__float_as_uint(t) < ALPHA_BITS) s += t;
}

// ---------------- fused stable counting sort (32 blocks, redundant scan) ----
__global__ void __launch_bounds__(512, 1) k_sort(const int* __restrict__ labels) {
    extern __shared__ int sm[];
    int* slab = sm;                 // [Nn]
    int* hist = sm + Nn;            // [NSEG][Cc]
    __shared__ int soff[Cc];
    __shared__ int wtot[16];
    int tid = threadIdx.x, seg = blockIdx.x;
    int lane = tid & 31, wrp = tid >> 5;

    if (seg == 0 && tid == 0) g_acc = 0.0;

    for (int q = tid; q < Nn; q += 512) slab[q] = labels[q];
    for (int q = tid; q < NSEG * Cc; q += 512) hist[q] = 0;
    __syncthreads();

    // full histogram: element e -> hist[seg(e)][label]
    for (int e = tid; e < Nn; e += 512)
        atomicAdd(&hist[(e >> 8) * Cc + slab[e]], 1);
    __syncthreads();

    // thread tid = label: prefix over segments, remember own-seg prefix
    int run = 0, mine = 0;
#pragma unroll
    for (int s = 0; s < NSEG; s++) {
        if (s == seg) mine = run;
        run += hist[s * Cc + tid];
    }
    int v = run;  // total for this label

    // inclusive warp-shuffle scan over 512 labels
#pragma unroll
    for (int o = 1; o < 32; o <<= 1) {
        int n = __shfl_up_sync(0xffffffffu, v, o);
        if (lane >= o) v += n;
    }
    if (lane == 31) wtot[wrp] = v;
    __syncthreads();
    if (wrp == 0) {
        int w = (lane < 16) ? wtot[lane] : 0;
#pragma unroll
        for (int o = 1; o < 16; o <<= 1) {
            int n = __shfl_up_sync(0xffffffffu, w, o);
            if (lane >= o) w += n;
        }
        if (lane < 16) wtot[lane] = w;
    }
    __syncthreads();
    int incl = v + (wrp ? wtot[wrp - 1] : 0);
    soff[tid] = (incl - run) + mine;      // global excl + own-seg prefix
    if (seg == 0) {
        g_offset[tid + 1] = incl;
        if (tid == 0) g_offset[0] = 0;
    }
    __syncthreads();

    // stable scatter of own segment
    if (tid < SEGSZ) {
        int idx = seg * SEGSZ + tid;
        int l = slab[idx];
        int r = 0;
        for (int p = seg * SEGSZ; p < idx; p++) r += (slab[p] == l);
        int pos = soff[l] + r;
        g_perm[pos] = idx;
        g_lab[pos]  = l;
    }
}

// ---------------- prep: 4 rows per warp, gather/split/norms/ap --------------
__global__ void __launch_bounds__(256, 8) k_prep(const float* __restrict__ X) {
    int wid = threadIdx.x >> 5, lane = threadIdx.x & 31;
    int row0 = blockIdx.x * 32 + wid * 4;

#pragma unroll
    for (int r = 0; r < 4; r++) {
        int row = row0 + r;
        int l = g_lab[row];
        int a = g_offset[l];
        int orig  = g_perm[row];
        int origA = g_perm[a];

        float4 v  = ((const float4*)(X + (size_t)orig  * Dd))[lane];
        float4 va = ((const float4*)(X + (size_t)origA * Dd))[lane];

        __nv_bfloat162 h01, h23, l01, l23;
        h01.x = __float2bfloat16(v.x); h01.y = __float2bfloat16(v.y);
        h23.x = __float2bfloat16(v.z); h23.y = __float2bfloat16(v.w);
        l01.x = __float2bfloat16(v.x - __bfloat162float(h01.x));
        l01.y = __float2bfloat16(v.y - __bfloat162float(h01.y));
        l23.x = __float2bfloat16(v.z - __bfloat162float(h23.x));
        l23.y = __float2bfloat16(v.w - __bfloat162float(h23.y));
        uint2 hi2 = make_uint2(*(uint32_t*)&h01, *(uint32_t*)&h23);
        uint2 lo2 = make_uint2(*(uint32_t*)&l01, *(uint32_t*)&l23);
        size_t b = (size_t)row * KSRC;
        *(uint2*)(g_Abuf + b + lane * 4)       = hi2;
        *(uint2*)(g_Abuf + b + 128 + lane * 4) = lo2;
        if (row == a) {
            size_t ba = (size_t)l * KSRC;
            *(uint2*)(g_Anc + ba + lane * 4)       = hi2;
            *(uint2*)(g_Anc + ba + 128 + lane * 4) = lo2;
        }

        float s1 = v.x * v.x + v.y * v.y + v.z * v.z + v.w * v.w;
        float s2 = va.x * va.x + va.y * va.y + va.z * va.z + va.w * va.w;
        float s3 = v.x * va.x + v.y * va.y + v.z * va.z + v.w * va.w;
#pragma unroll
        for (int o = 16; o > 0; o >>= 1) {
            s1 += __shfl_down_sync(0xffffffffu, s1, o);
            s2 += __shfl_down_sync(0xffffffffu, s2, o);
            s3 += __shfl_down_sync(0xffffffffu, s3, o);
        }
        if (lane == 0) {
            g_sq[row]  = s1;
            g_ap[row]  = s2 + s1 - 2.0f * s3;
            g_pos[row] = (row != a) ? 1 : 0;
            if (row == a) g_sqA[l] = s1;
        }
    }
}

// ---------------- fused: anchor blocks (0..255) + main tiles (256..2335) ----
__global__ void __launch_bounds__(256, 2) k_fused() {
    extern __shared__ char dynsm[];
    __shared__ float sSqI[128], sSqJ[128], sApIA[128], sApJA[128];
    __shared__ int   sLabI[128], sLabJ[128];
    __shared__ int   sOff[129];
    __shared__ float sSqA[128];
    __shared__ float warpsum[8];

    int tid = threadIdx.x;
    int wid = tid >> 5, lane = tid & 31;
    int wm = wid & 3, wn = wid >> 2;
    int lrow = lane & 15, lkh = lane >> 4;
    int tg = lane & 3, gID = lane >> 2;

    int bid = blockIdx.x;
    int is_anch = (bid < NANCH);
    int i0 = 0, j0, l0 = 0, by = 0, bx = 0, offdiag = 0;
    const __nv_bfloat16 *aSrc, *bSrc;

    if (is_anch) {
        j0 = (bid & 63) * 128;
        l0 = (bid >> 6) * 128;
        aSrc = g_Anc  + (size_t)l0 * KSRC;
        bSrc = g_Abuf + (size_t)j0 * KSRC;
    } else {
        int t = bid - NANCH;
        by = (int)(0.5f * (129.0f - sqrtf(16641.0f - 8.0f * (float)t)));
        while ((by + 1) * NTILE - (((by + 1) * by) >> 1) <= t) by++;
        while (by * NTILE - ((by * (by - 1)) >> 1) > t) by--;
        bx = by + t - (by * NTILE - ((by * (by - 1)) >> 1));
        i0 = by * 128; j0 = bx * 128;
        offdiag = (bx != by);
        aSrc = g_Abuf + (size_t)i0 * KSRC;
        bSrc = g_Abuf + (size_t)j0 * KSRC;
    }

    uint32_t dbase = smem_u32(dynsm);
    uint32_t smBase = (dbase + 1023u) & ~1023u;

    if (is_anch) {
        if (tid < 129) sOff[tid] = g_offset[l0 + tid];
        if (tid < 128) sSqJ[tid] = g_sq[j0 + tid];
        else if (tid >= 128) sSqA[tid - 128] = g_sqA[l0 + tid - 128];
    } else {
        if (tid < 128) {
            int i = i0 + tid;
            sSqI[tid]  = g_sq[i];
            sLabI[tid] = g_lab[i];
            sApIA[tid] = g_pos[i] ? (g_ap[i] + ALPHA) : -1e30f;
        } else {
            int tt2 = tid - 128;
            int j = j0 + tt2;
            sSqJ[tt2]  = g_sq[j];
            sLabJ[tt2] = g_lab[j];
            sApJA[tt2] = (offdiag && g_pos[j]) ? (g_ap[j] + ALPHA) : -1e30f;
        }
    }

    float acc[2][8][4];
#pragma unroll
    for (int a = 0; a < 2; a++)
#pragma unroll
        for (int b = 0; b < 8; b++)
#pragma unroll
            for (int e = 0; e < 4; e++) acc[a][b][e] = 0.0f;

    int lr[4], ls[4];
    uint32_t loff[4];
#pragma unroll
    for (int p = 0; p < 4; p++) {
        int q = tid + p * 256;
        lr[p] = q >> 3;
        ls[p] = q & 7;
        loff[p] = (uint32_t)lr[p] * 128u + (((uint32_t)ls[p] * 16u) ^ (((uint32_t)lr[p] & 7u) << 4));
    }

    // prefetch chunks 0,1
#pragma unroll
    for (int c0 = 0; c0 < NSTAGE - 1; c0++) {
        uint32_t sA = smBase + (uint32_t)c0 * 2u * TILEB;
        uint32_t sB = sA + TILEB;
        int kk = c0 * BK;
#pragma unroll
        for (int p = 0; p < 4; p++) {
            cpasync16(sA + loff[p], aSrc + (size_t)lr[p] * KSRC + kk + ls[p] * 8);
            cpasync16(sB + loff[p], bSrc + (size_t)lr[p] * KSRC + kk + ls[p] * 8);
        }
        cp_commit();
    }

    int arow = wm * 32 + lrow;
    uint32_t aOff = (uint32_t)arow * 128u;
    uint32_t aXor = ((uint32_t)arow & 7u) << 4;

    // single-sync pipeline: [cp_wait][sync][issue c+2][consume c]
    for (int c = 0; c < KCHUNKS; c++) {
        if (c < KCHUNKS - 1) cp_wait<NSTAGE - 2>();
        else                 cp_wait<0>();
        __syncthreads();
        if (c + NSTAGE - 1 < KCHUNKS) {
            int cn = c + NSTAGE - 1;
            int kk = cn * BK;
            uint32_t sA = smBase + (uint32_t)(cn % NSTAGE) * 2u * TILEB;
            uint32_t sB = sA + TILEB;
#pragma unroll
            for (int p = 0; p < 4; p++) {
                cpasync16(sA + loff[p], aSrc + (size_t)lr[p] * KSRC + kk + ls[p] * 8);
                cpasync16(sB + loff[p], bSrc + (size_t)lr[p] * KSRC + kk + ls[p] * 8);
            }
            cp_commit();
        }

        uint32_t aB = smBase + (uint32_t)(c % NSTAGE) * 2u * TILEB;
        uint32_t bB = aB + TILEB;
#pragma unroll
        for (int ks = 0; ks < 4; ks++) {
            uint32_t koff = (uint32_t)(ks * 32 + lkh * 16);
            uint32_t a0[2], a1[2], a2[2], a3[2];
#pragma unroll
            for (int mi = 0; mi < 2; mi++)
                ldm_x4(a0[mi], a1[mi], a2[mi], a3[mi],
                       aB + aOff + (uint32_t)mi * 2048u + (koff ^ aXor));
#pragma unroll
            for (int g2 = 0; g2 < 4; g2++) {
                int brow = wn * 64 + g2 * 16 + lrow;
                uint32_t r0, r1, r2, r3;
                ldm_x4(r0, r1, r2, r3,
                       bB + (uint32_t)brow * 128u + (koff ^ (((uint32_t)brow & 7u) << 4)));
#pragma unroll
                for (int mi = 0; mi < 2; mi++) {
                    mma16816(acc[mi][2 * g2],     a0[mi], a1[mi], a2[mi], a3[mi], r0, r2);
                    mma16816(acc[mi][2 * g2 + 1], a0[mi], a1[mi], a2[mi], a3[mi], r1, r3);
                }
            }
        }
    }

    float csum0 = 0.0f, csum1 = 0.0f;

    if (is_anch) {
        // all warps must finish reading tile smem before reuse for sap
        __syncthreads();
        float* sap = (float*)dynsm;
        int apbase = sOff[0];
        int apcnt  = sOff[128] - apbase;
        for (int q = tid; q < apcnt; q += 256) sap[q] = g_ap[apbase + q];
        __syncthreads();

#pragma unroll
        for (int ridx = 0; ridx < 4; ridx++) {
            int mi = ridx >> 1, e2 = ridx & 1;
            int row = wm * 32 + mi * 16 + gID + e2 * 8;
            int s0 = sOff[row], s1 = sOff[row + 1];
            int m = s1 - s0 - 1;
            if (m > 0) {
                float nsqaA = ALPHA - sSqA[row];
                float negD[16];
#pragma unroll
                for (int ni = 0; ni < 8; ni++)
#pragma unroll
                    for (int e1 = 0; e1 < 2; e1++) {
                        int col = wn * 64 + ni * 8 + 2 * tg + e1;
                        int j = j0 + col;
                        float nd = fmaf(2.0f, acc[mi][ni][e2 * 2 + e1], nsqaA - sSqJ[col]);
                        negD[ni * 2 + e1] = (j >= s0 && j < s1) ? -1e30f : nd;
                    }
                int qb = s0 - apbase + 1;
                for (int q = 0; q < m; q++) {
                    float apq = sap[qb + q];
#pragma unroll
                    for (int c16 = 0; c16 < 16; c16 += 2) {
                        hinge(apq + negD[c16],     csum0);
                        hinge(apq + negD[c16 + 1], csum1);
                    }
                }
            }
        }
    } else {
        float rSq[4], rC[4];
        int   rLab[4];
#pragma unroll
        for (int mi = 0; mi < 2; mi++)
#pragma unroll
            for (int e2 = 0; e2 < 2; e2++) {
                int ridx = mi * 2 + e2;
                int row = wm * 32 + mi * 16 + gID + e2 * 8;
                rSq[ridx]  = sSqI[row];
                rLab[ridx] = sLabI[row];
                rC[ridx]   = sApIA[row] - rSq[ridx];
            }

        int collide = (by == bx) || (sLabI[127] == sLabJ[0]);

        if (!collide) {
#pragma unroll
            for (int ni = 0; ni < 8; ni++)
#pragma unroll
                for (int e1 = 0; e1 < 2; e1++) {
                    int col = wn * 64 + ni * 8 + 2 * tg + e1;
                    float cSq = sSqJ[col];
                    float cC  = sApJA[col] - cSq;
#pragma unroll
                    for (int mi = 0; mi < 2; mi++)
#pragma unroll
                        for (int e2 = 0; e2 < 2; e2++) {
                            int ridx = mi * 2 + e2;
                            float av = acc[mi][ni][e2 * 2 + e1];
                            hinge(fmaf(2.0f, av, rC[ridx] - cSq), csum0);
                            hinge(fmaf(2.0f, av, cC - rSq[ridx]), csum1);
                        }
                }
        } else {
#pragma unroll
            for (int ni = 0; ni < 8; ni++)
#pragma unroll
                for (int e1 = 0; e1 < 2; e1++) {
                    int col = wn * 64 + ni * 8 + 2 * tg + e1;
                    float cSq = sSqJ[col];
                    float cC  = sApJA[col] - cSq;
                    int   cLab = sLabJ[col];
#pragma unroll
                    for (int mi = 0; mi < 2; mi++)
#pragma unroll
                        for (int e2 = 0; e2 < 2; e2++) {
                            int ridx = mi * 2 + e2;
                            if (rLab[ridx] == cLab) continue;
                            float av = acc[mi][ni][e2 * 2 + e1];
                            hinge(fmaf(2.0f, av, rC[ridx] - cSq), csum0);
                            hinge(fmaf(2.0f, av, cC - rSq[ridx]), csum1);
                        }
                }
        }
    }

    float csum = csum0 + csum1;
#pragma unroll
    for (int o = 16; o > 0; o >>= 1) csum += __shfl_down_sync(0xffffffffu, csum, o);
    if (lane == 0) warpsum[wid] = csum;
    __syncthreads();
    if (wid == 0) {
        float tt2 = (lane < 8) ? warpsum[lane] : 0.0f;
#pragma unroll
        for (int o = 4; o > 0; o >>= 1) tt2 += __shfl_down_sync(0xffffffffu, tt2, o);
        if (lane == 0) atomicAdd(&g_acc, (double)tt2);
    }
}

__global__ void k_out(float* __restrict__ out) {
    if (threadIdx.x == 0) out[0] = (float)g_acc;
}

// ---------------- launch ----------------
extern "C" void kernel_launch(void* const* d_in, const int* in_sizes, int n_in,
                              void* d_out, int out_size) {
    const float* X      = (const float*)d_in[0];
    const int*   labels = (const int*)d_in[1];

    static int smem_set = 0;
    if (!smem_set) {
        cudaFuncSetAttribute(k_fused, cudaFuncAttributeMaxDynamicSharedMemorySize, DYN_SMEM);
        cudaFuncSetAttribute(k_sort,  cudaFuncAttributeMaxDynamicSharedMemorySize, SORT_SMEM);
        smem_set = 1;
    }

    int nmain = (NTILE * (NTILE + 1)) / 2;
    k_sort <<<NSEG, 512, SORT_SMEM>>>(labels);           // 0
    k_prep <<<Nn / 32, 256>>>(X);                        // 1
    k_fused<<<NANCH + nmain, 256, DYN_SMEM>>>();         // 2
    k_out  <<<1, 32>>>((float*)d_out);                   // 3
}